// round 16
// baseline (speedup 1.0000x reference)
#include <cuda_runtime.h>
#include <cuda_bf16.h>
#include <cstdint>

// Problem constants
#define BB 4
#define TT 4096
#define CC 1024
#define HH 128

// ---------------------------------------------------------------------------
// Device scratch (no allocations allowed). Q/K/V live ONLY as split bf16.
// ---------------------------------------------------------------------------
__device__ __nv_bfloat16 g_Qhi[BB * TT * HH];
__device__ __nv_bfloat16 g_Qlo[BB * TT * HH];
__device__ __nv_bfloat16 g_Khi[BB * TT * HH];
__device__ __nv_bfloat16 g_Klo[BB * TT * HH];
__device__ __nv_bfloat16 g_Vhi[BB * TT * HH];
__device__ __nv_bfloat16 g_Vlo[BB * TT * HH];
__device__ __nv_bfloat16 g_Bhi[3 * HH * CC];        // W^T split-hi [3][128][1024]
__device__ __nv_bfloat16 g_Blo[3 * HH * CC];        // W^T split-lo

// ---------------------------------------------------------------------------
// Helpers (baseline sm_100 PTX: ldmatrix + mma.sync + cp.async)
// ---------------------------------------------------------------------------
__device__ __forceinline__ uint32_t smem_u32(const void* p) {
    uint32_t a;
    asm("{ .reg .u64 t; cvta.to.shared.u64 t, %1; cvt.u32.u64 %0, t; }"
        : "=r"(a) : "l"(p));
    return a;
}

#define LDMX4(r, addr) \
    asm volatile("ldmatrix.sync.aligned.m8n8.x4.shared.b16 {%0,%1,%2,%3}, [%4];" \
        : "=r"((r)[0]), "=r"((r)[1]), "=r"((r)[2]), "=r"((r)[3]) : "r"(addr))

#define LDMX4T(r, addr) \
    asm volatile("ldmatrix.sync.aligned.m8n8.x4.trans.shared.b16 {%0,%1,%2,%3}, [%4];" \
        : "=r"((r)[0]), "=r"((r)[1]), "=r"((r)[2]), "=r"((r)[3]) : "r"(addr))

#define MMA_BF16(c, a, b0, b1) \
    asm volatile("mma.sync.aligned.m16n8k16.row.col.f32.bf16.bf16.f32 " \
        "{%0,%1,%2,%3}, {%4,%5,%6,%7}, {%8,%9}, {%0,%1,%2,%3};" \
        : "+f"((c)[0]), "+f"((c)[1]), "+f"((c)[2]), "+f"((c)[3]) \
        : "r"((a)[0]), "r"((a)[1]), "r"((a)[2]), "r"((a)[3]), "r"(b0), "r"(b1))

#define CP_ASYNC16(saddr, gptr) \
    asm volatile("cp.async.cg.shared.global [%0], [%1], 16;" \
        :: "r"(saddr), "l"(gptr) : "memory")
#define CP_COMMIT() asm volatile("cp.async.commit_group;" ::: "memory")
#define CP_WAIT0()  asm volatile("cp.async.wait_group 0;" ::: "memory")

__device__ __forceinline__ uint32_t pack_bf2(__nv_bfloat16 a, __nv_bfloat16 b) {
    return (uint32_t)__bfloat16_as_ushort(a) |
           ((uint32_t)__bfloat16_as_ushort(b) << 16);
}
__device__ __forceinline__ void split2(float a, float b, uint32_t& hi, uint32_t& lo) {
    __nv_bfloat16 h0 = __float2bfloat16(a), h1 = __float2bfloat16(b);
    hi = pack_bf2(h0, h1);
    lo = pack_bf2(__float2bfloat16(a - __bfloat162float(h0)),
                  __float2bfloat16(b - __bfloat162float(h1)));
}

// ---------------------------------------------------------------------------
// Transpose + split W [1024,128] -> W^T [128,1024] bf16 hi/lo. (unchanged)
// ---------------------------------------------------------------------------
__global__ __launch_bounds__(256) void transpose_w(
    const float* __restrict__ Wq, const float* __restrict__ Wk,
    const float* __restrict__ Wv)
{
    const int w = blockIdx.y;
    const float* src = (w == 0) ? Wq : (w == 1) ? Wk : Wv;
    const int idx = blockIdx.x * 256 + threadIdx.x;   // 0..131071
    const int n = idx >> 10;
    const int k = idx & 1023;
    const float v = src[(size_t)k * HH + n];
    __nv_bfloat16 h = __float2bfloat16(v);
    g_Bhi[(size_t)w * HH * CC + idx] = h;
    g_Blo[(size_t)w * HH * CC + idx] = __float2bfloat16(v - __bfloat162float(h));
}

// ---------------------------------------------------------------------------
// HMMA projection GEMM with FUSED fp32->split-bf16 conversion of X. (unchanged)
// ---------------------------------------------------------------------------
#define PADK       40
#define TILE_BYTES (128 * PADK * 2)
#define BUF_BYTES  (4 * TILE_BYTES)
#define GEMM_SMEM  (2 * BUF_BYTES)

struct StageRegs {
    float4 xa[2], xb[2];
    uint4  bh[2], bl[2];
};

__global__ __launch_bounds__(256) void gemm_proj(const float* __restrict__ X)
{
    extern __shared__ __align__(16) char smem[];
    const uint32_t sb = smem_u32(smem);
    const int tid  = threadIdx.x;
    const int w    = tid >> 5;
    const int lane = tid & 31;
    const int mt   = blockIdx.x;
    const int wt   = blockIdx.y;

    const __nv_bfloat16* Bh = g_Bhi + (size_t)wt * HH * CC;
    const __nv_bfloat16* Bl = g_Blo + (size_t)wt * HH * CC;
    __nv_bfloat16* Oh = (wt == 0) ? g_Qhi : (wt == 1) ? g_Khi : g_Vhi;
    __nv_bfloat16* Ol = (wt == 0) ? g_Qlo : (wt == 1) ? g_Klo : g_Vlo;

    const size_t arow0 = (size_t)mt * 128;

    float acc[16][4];
    #pragma unroll
    for (int i = 0; i < 16; ++i)
        #pragma unroll
        for (int j = 0; j < 4; ++j) acc[i][j] = 0.f;

    auto ld_regs = [&](StageRegs& r, int s) {
        const int k0 = s * 32;
        #pragma unroll
        for (int h = 0; h < 2; ++h) {
            const int c   = tid + h * 256;
            const int row = c >> 2;
            const int ke  = (c & 3) * 8;
            const float* xp = X + (arow0 + row) * CC + k0 + ke;
            r.xa[h] = *(const float4*)xp;
            r.xb[h] = *(const float4*)(xp + 4);
            r.bh[h] = *(const uint4*)(Bh + (size_t)row * CC + k0 + ke);
            r.bl[h] = *(const uint4*)(Bl + (size_t)row * CC + k0 + ke);
        }
    };
    auto st_smem = [&](const StageRegs& r, int buf_i) {
        const uint32_t buf = (uint32_t)buf_i * BUF_BYTES;
        #pragma unroll
        for (int h = 0; h < 2; ++h) {
            const int c   = tid + h * 256;
            const int row = c >> 2;
            const int ke  = (c & 3) * 8;
            const uint32_t so = buf + (uint32_t)(row * PADK + ke) * 2;
            uint4 ahi, alo;
            split2(r.xa[h].x, r.xa[h].y, ahi.x, alo.x);
            split2(r.xa[h].z, r.xa[h].w, ahi.y, alo.y);
            split2(r.xb[h].x, r.xb[h].y, ahi.z, alo.z);
            split2(r.xb[h].z, r.xb[h].w, ahi.w, alo.w);
            *(uint4*)(smem + so)                  = ahi;
            *(uint4*)(smem + so + TILE_BYTES)     = alo;
            *(uint4*)(smem + so + 2 * TILE_BYTES) = r.bh[h];
            *(uint4*)(smem + so + 3 * TILE_BYTES) = r.bl[h];
        }
    };

    const int lrow  = lane & 15;
    const int lcol8 = (lane >> 4) * 8;

    {
        StageRegs r0;
        ld_regs(r0, 0);
        st_smem(r0, 0);
    }
    __syncthreads();

    for (int s = 0; s < 32; ++s) {
        StageRegs nxt;
        if (s + 1 < 32) ld_regs(nxt, s + 1);
        const uint32_t buf = sb + (uint32_t)(s & 1) * BUF_BYTES;
        #pragma unroll
        for (int kk = 0; kk < 32; kk += 16) {
            const uint32_t aaddr =
                buf + (uint32_t)((16 * w + lrow) * PADK + kk + lcol8) * 2;
            uint32_t ah[4], al[4];
            LDMX4(ah, aaddr);
            LDMX4(al, aaddr + TILE_BYTES);
            #pragma unroll
            for (int j = 0; j < 8; ++j) {
                const uint32_t baddr = buf + 2 * TILE_BYTES +
                    (uint32_t)((16 * j + lrow) * PADK + kk + lcol8) * 2;
                uint32_t bh[4], bl[4];
                LDMX4(bh, baddr);
                LDMX4(bl, baddr + TILE_BYTES);
                MMA_BF16(acc[2 * j],     ah, bh[0], bh[2]);
                MMA_BF16(acc[2 * j],     ah, bl[0], bl[2]);
                MMA_BF16(acc[2 * j],     al, bh[0], bh[2]);
                MMA_BF16(acc[2 * j + 1], ah, bh[1], bh[3]);
                MMA_BF16(acc[2 * j + 1], ah, bl[1], bl[3]);
                MMA_BF16(acc[2 * j + 1], al, bh[1], bh[3]);
            }
        }
        if (s + 1 < 32) st_smem(nxt, (s + 1) & 1);
        __syncthreads();
    }

    const int m0 = 16 * w + (lane >> 2);
    const int nc = (lane & 3) * 2;
    #pragma unroll
    for (int nt = 0; nt < 16; ++nt) {
        uint32_t hi, lo;
        split2(acc[nt][0], acc[nt][1], hi, lo);
        *(uint32_t*)&Oh[(arow0 + m0) * HH + nt * 8 + nc] = hi;
        *(uint32_t*)&Ol[(arow0 + m0) * HH + nt * 8 + nc] = lo;
        split2(acc[nt][2], acc[nt][3], hi, lo);
        *(uint32_t*)&Oh[(arow0 + m0 + 8) * HH + nt * 8 + nc] = hi;
        *(uint32_t*)&Ol[(arow0 + m0 + 8) * HH + nt * 8 + nc] = lo;
    }
}

// ---------------------------------------------------------------------------
// HMMA flash attention, 2 CTAs/SM:
//   - warp-local online softmax (each warp owns a 32-col half; own m/l;
//     m init -6e29 so fully-masked halves contribute p=0) -> NO cross-warp
//     reduction, 2 barriers/iter.
//   - split-K PV: own P frags stay in registers (S C-frag == PV A-frag);
//     each warp accumulates partial O over its 32 s-cols x all 128 h.
//   - exact log-sum-exp combine of the two column-half partials in epilogue.
//   - smem = 6 tiles (K/Q/V hi+lo) = 104448 B -> 2 CTAs per SM.
// Grid (64 t-tiles, 4 batches) = 256 CTAs; it = 63 - bid (big tiles first).
// scores[t,s] = k[t]·q[s]/32, s <= t. 256 thr / 8 warps, 64x64 tiles, D=128.
// ---------------------------------------------------------------------------
#define PADL 136
#define E_KH 0
#define E_KL 8704
#define E_QH 17408
#define E_QL 26112
#define E_VH 34816
#define E_VL 43520
#define ATT_SMEM 104448                // 52224 bf16 elems * 2
#define MNEG (-6e29f)

__global__ __launch_bounds__(256, 2) void attn_kernel(float* __restrict__ out)
{
    extern __shared__ __align__(16) char sm[];
    const uint32_t sb = smem_u32(sm);

    const int b    = blockIdx.y;
    const int it   = 63 - blockIdx.x;   // big tiles first
    const int tid  = threadIdx.x;
    const int lane = tid & 31;
    const int wid  = tid >> 5;
    const int wr   = wid & 3;           // row group: rows 16*wr..16*wr+15
    const int wc   = wid >> 2;          // column half: 0..1 (s-cols 32*wc..)

    const size_t bo = (size_t)b * TT * HH;
    const __nv_bfloat16* Qh = g_Qhi + bo;
    const __nv_bfloat16* Ql = g_Qlo + bo;
    const __nv_bfloat16* Kh = g_Khi + bo;
    const __nv_bfloat16* Kl = g_Klo + bo;
    const __nv_bfloat16* Vh = g_Vhi + bo;
    const __nv_bfloat16* Vl = g_Vlo + bo;

    const int lrow  = lane & 15;
    const int lcol8 = (lane >> 4) * 8;
    const int r1    = 16 * wr + (lane >> 2);   // local row (also r1+8)
    const int cpair = (lane & 3) * 2;
    const int t0    = it * 64;

    // async-copy one 64x128 bf16 tile into smem (stride PADL)
    auto cp_tile = [&](uint32_t dstE, const __nv_bfloat16* src) {
        #pragma unroll
        for (int h = 0; h < 4; ++h) {
            const int c = tid + h * 256;            // 0..1023
            const int row = c >> 4, ch = (c & 15) * 8;
            CP_ASYNC16(sb + (uint32_t)(dstE + row * PADL + ch) * 2,
                       src + row * HH + ch);
        }
    };

    cp_tile(E_KH, Kh + (size_t)t0 * HH);
    cp_tile(E_KL, Kl + (size_t)t0 * HH);
    cp_tile(E_QH, Qh);
    cp_tile(E_QL, Ql);
    cp_tile(E_VH, Vh);
    cp_tile(E_VL, Vl);
    CP_COMMIT();

    float m0 = MNEG, m1 = MNEG, l0 = 0.f, l1 = 0.f;
    float accO[16][4];
    #pragma unroll
    for (int i = 0; i < 16; ++i)
        #pragma unroll
        for (int j = 0; j < 4; ++j) accO[i][j] = 0.f;

    for (int j = 0; j <= it; ++j) {
        CP_WAIT0();
        __syncthreads();                 // tiles visible

        // ---- S = K @ Q^T (rows 16*wr.., own cols 32*wc..), split-bf16 ----
        float accS[4][4];
        #pragma unroll
        for (int i = 0; i < 4; ++i)
            #pragma unroll
            for (int jj = 0; jj < 4; ++jj) accS[i][jj] = 0.f;

        #pragma unroll
        for (int kk = 0; kk < 128; kk += 16) {
            const uint32_t ka = sb +
                (uint32_t)((16 * wr + lrow) * PADL + kk + lcol8) * 2;
            uint32_t ah[4], al[4];
            LDMX4(ah, ka + E_KH * 2);
            LDMX4(al, ka + E_KL * 2);
            #pragma unroll
            for (int n2 = 0; n2 < 2; ++n2) {
                const uint32_t qa = sb +
                    (uint32_t)((32 * wc + 16 * n2 + lrow) * PADL + kk + lcol8) * 2;
                uint32_t qh[4], ql[4];
                LDMX4(qh, qa + E_QH * 2);
                LDMX4(ql, qa + E_QL * 2);
                MMA_BF16(accS[2 * n2],     ah, qh[0], qh[2]);
                MMA_BF16(accS[2 * n2],     ah, ql[0], ql[2]);
                MMA_BF16(accS[2 * n2],     al, qh[0], qh[2]);
                MMA_BF16(accS[2 * n2 + 1], ah, qh[1], qh[3]);
                MMA_BF16(accS[2 * n2 + 1], ah, ql[1], ql[3]);
                MMA_BF16(accS[2 * n2 + 1], al, qh[1], qh[3]);
            }
        }

        // ---- scale + causal mask ----
        const bool diag = (j == it);
        #pragma unroll
        for (int nt = 0; nt < 4; ++nt)
            #pragma unroll
            for (int e = 0; e < 2; ++e) {
                const int col = 32 * wc + nt * 8 + cpair + e;
                float v0 = accS[nt][e]     * 0.03125f;
                float v1 = accS[nt][e + 2] * 0.03125f;
                if (diag && col > r1)     v0 = -1e30f;
                if (diag && col > r1 + 8) v1 = -1e30f;
                accS[nt][e]     = v0;
                accS[nt][e + 2] = v1;
            }

        // ---- warp-local row max over own 32 cols (quad shuffle) ----
        float pm0 = -1e30f, pm1 = -1e30f;
        #pragma unroll
        for (int nt = 0; nt < 4; ++nt) {
            pm0 = fmaxf(pm0, fmaxf(accS[nt][0], accS[nt][1]));
            pm1 = fmaxf(pm1, fmaxf(accS[nt][2], accS[nt][3]));
        }
        #pragma unroll
        for (int off = 1; off <= 2; off <<= 1) {
            pm0 = fmaxf(pm0, __shfl_xor_sync(0xffffffffu, pm0, off));
            pm1 = fmaxf(pm1, __shfl_xor_sync(0xffffffffu, pm1, off));
        }
        const float mn0 = fmaxf(m0, pm0);   // >= MNEG; all-masked stays MNEG
        const float mn1 = fmaxf(m1, pm1);

        // ---- exp + in-register P fragments + row sums ----
        float ps0 = 0.f, ps1 = 0.f;
        uint32_t pfh[2][4], pfl[2][4];   // own A-frags for 2 k-chunks of 16 s
        #pragma unroll
        for (int nt = 0; nt < 4; ++nt) {
            float p00 = __expf(accS[nt][0] - mn0);
            float p01 = __expf(accS[nt][1] - mn0);
            float p10 = __expf(accS[nt][2] - mn1);
            float p11 = __expf(accS[nt][3] - mn1);
            ps0 += p00 + p01;
            ps1 += p10 + p11;
            uint32_t hiR, loR, hiR8, loR8;
            split2(p00, p01, hiR, loR);      // row r1   -> frag a0/a2
            split2(p10, p11, hiR8, loR8);    // row r1+8 -> frag a1/a3
            const int cL = nt >> 1;
            const int sl = (nt & 1) * 2;
            pfh[cL][sl]     = hiR;
            pfh[cL][sl + 1] = hiR8;
            pfl[cL][sl]     = loR;
            pfl[cL][sl + 1] = loR8;
        }
        #pragma unroll
        for (int off = 1; off <= 2; off <<= 1) {
            ps0 += __shfl_xor_sync(0xffffffffu, ps0, off);
            ps1 += __shfl_xor_sync(0xffffffffu, ps1, off);
        }
        const float c0 = __expf(m0 - mn0);
        const float c1 = __expf(m1 - mn1);
        l0 = l0 * c0 + ps0;
        l1 = l1 * c1 + ps1;
        m0 = mn0;
        m1 = mn1;

        // ---- O rescale + partial O += P_own @ V (own 32 s, all 128 h) ----
        #pragma unroll
        for (int nt = 0; nt < 16; ++nt) {
            accO[nt][0] *= c0; accO[nt][1] *= c0;
            accO[nt][2] *= c1; accO[nt][3] *= c1;
        }
        #pragma unroll
        for (int cL = 0; cL < 2; ++cL) {
            const int k2 = 32 * wc + 16 * cL;
            #pragma unroll
            for (int hg = 0; hg < 8; ++hg) {
                const uint32_t va = sb +
                    (uint32_t)((k2 + lrow) * PADL + hg * 16 + lcol8) * 2;
                uint32_t vh[4], vl[4];
                LDMX4T(vh, va + E_VH * 2);
                LDMX4T(vl, va + E_VL * 2);
                MMA_BF16(accO[2 * hg],     pfh[cL], vh[0], vh[1]);
                MMA_BF16(accO[2 * hg],     pfh[cL], vl[0], vl[1]);
                MMA_BF16(accO[2 * hg],     pfl[cL], vh[0], vh[1]);
                MMA_BF16(accO[2 * hg + 1], pfh[cL], vh[2], vh[3]);
                MMA_BF16(accO[2 * hg + 1], pfh[cL], vl[2], vl[3]);
                MMA_BF16(accO[2 * hg + 1], pfl[cL], vh[2], vh[3]);
            }
        }

        __syncthreads();                 // all warps done reading Q/V tiles
        if (j < it) {                    // load next Q/V into same buffer
            const size_t s1 = (size_t)(j + 1) * 64 * HH;
            cp_tile(E_QH, Qh + s1);
            cp_tile(E_QL, Ql + s1);
            cp_tile(E_VH, Vh + s1);
            cp_tile(E_VL, Vl + s1);
            CP_COMMIT();
        }
    }

    // ---- epilogue: combine the two column-half partials, normalize ----
    float* smO = (float*)sm;             // [64][132] fp32 (reuses K area+)
    float* smM = (float*)(sm + 69632);   // [64]
    float* smL = smM + 64;               // [64]
    if (wc == 1) {
        #pragma unroll
        for (int nt = 0; nt < 16; ++nt) {
            const int h0 = nt * 8 + cpair;
            smO[r1 * 132 + h0]           = accO[nt][0];
            smO[r1 * 132 + h0 + 1]       = accO[nt][1];
            smO[(r1 + 8) * 132 + h0]     = accO[nt][2];
            smO[(r1 + 8) * 132 + h0 + 1] = accO[nt][3];
        }
        if ((lane & 3) == 0) {
            smM[r1] = m0;      smL[r1] = l0;
            smM[r1 + 8] = m1;  smL[r1 + 8] = l1;
        }
    }
    __syncthreads();
    if (wc == 0) {
        const float mB0 = smM[r1],     lB0 = smL[r1];
        const float mB1 = smM[r1 + 8], lB1 = smL[r1 + 8];
        const float ms0 = fmaxf(m0, mB0);
        const float ms1 = fmaxf(m1, mB1);
        const float fA0 = __expf(m0 - ms0), fB0 = __expf(mB0 - ms0);
        const float fA1 = __expf(m1 - ms1), fB1 = __expf(mB1 - ms1);
        const float inv0 = 1.f / (l0 * fA0 + lB0 * fB0);
        const float inv1 = 1.f / (l1 * fA1 + lB1 * fB1);
        float* ob = out + ((size_t)b * TT + t0) * HH;
        #pragma unroll
        for (int nt = 0; nt < 16; ++nt) {
            const int h0 = nt * 8 + cpair;
            float2 o0 = {
                (accO[nt][0] * fA0 + smO[r1 * 132 + h0]     * fB0) * inv0,
                (accO[nt][1] * fA0 + smO[r1 * 132 + h0 + 1] * fB0) * inv0};
            float2 o1 = {
                (accO[nt][2] * fA1 + smO[(r1 + 8) * 132 + h0]     * fB1) * inv1,
                (accO[nt][3] * fA1 + smO[(r1 + 8) * 132 + h0 + 1] * fB1) * inv1};
            *(float2*)&ob[(size_t)r1 * HH + h0]       = o0;
            *(float2*)&ob[(size_t)(r1 + 8) * HH + h0] = o1;
        }
    }
}

// ---------------------------------------------------------------------------
// Launch
// ---------------------------------------------------------------------------
extern "C" void kernel_launch(void* const* d_in, const int* in_sizes, int n_in,
                              void* d_out, int out_size)
{
    const float* ix = (const float*)d_in[0];
    const float* Wq = (const float*)d_in[1];
    const float* Wk = (const float*)d_in[2];
    const float* Wv = (const float*)d_in[3];
    float* out = (float*)d_out;

    // 1. Split weights (tiny)
    transpose_w<<<dim3((HH * CC) / 256, 3), 256>>>(Wq, Wk, Wv);

    // 2. HMMA projection GEMMs with fused fp32->split-bf16 conversion
    cudaFuncSetAttribute(gemm_proj, cudaFuncAttributeMaxDynamicSharedMemorySize,
                         GEMM_SMEM);
    gemm_proj<<<dim3(128, 3), 256, GEMM_SMEM>>>(ix);

    // 3. HMMA flash attention: warp-local softmax, 2 CTAs/SM, 256 CTAs
    cudaFuncSetAttribute(attn_kernel, cudaFuncAttributeMaxDynamicSharedMemorySize,
                         ATT_SMEM);
    attn_kernel<<<dim3(64, 4), 256, ATT_SMEM>>>(out);
}